// round 11
// baseline (speedup 1.0000x reference)
#include <cuda_runtime.h>
#include <cuda_fp16.h>
#include <math.h>
#include <stdint.h>

// Problem constants: B=8, C=256, H=W=256, WS=8, HEADS=4, dh=64
#define HW  65536
#define IMW 256

// fp16 fragment-packed scratch (all m16n8k16 layouts), stored as u32 (half2):
//  h_qkv: Q | K | V regions, 2048 words per (b,hd,win) unit.
//  h_x / h_attn (GEMM B): [b][t8 8192][s 8][lane*4 + ks*2 + r] (pairs over chan)
//  h_wq / h_wp (GEMM A): [mt][k16 16][lane*4 + hik*2 + him]
__device__ uint32_t h_qkv[201326592];
__device__ uint32_t h_x[67108864];
__device__ uint32_t h_attn[67108864];
__device__ uint32_t h_wq[98304];
__device__ uint32_t h_wp[32768];

#define KOFF 67108864
#define VOFF 134217728

__device__ __forceinline__ uint32_t smem_u32(const void* p) {
    uint32_t a;
    asm("{ .reg .u64 t; cvta.to.shared.u64 t, %1; cvt.u32.u64 %0, t; }" : "=r"(a) : "l"(p));
    return a;
}

__device__ __forceinline__ uint32_t h2(float lo, float hi) {
    __half2 h = __floats2half2_rn(lo, hi);
    return *(uint32_t*)&h;
}

__device__ __forceinline__ void mma16(float c[4],
                                      uint32_t a0, uint32_t a1, uint32_t a2, uint32_t a3,
                                      uint32_t b0, uint32_t b1) {
    asm volatile(
        "mma.sync.aligned.m16n8k16.row.col.f32.f16.f16.f32 "
        "{%0,%1,%2,%3}, {%4,%5,%6,%7}, {%8,%9}, {%0,%1,%2,%3};"
        : "+f"(c[0]), "+f"(c[1]), "+f"(c[2]), "+f"(c[3])
        : "r"(a0), "r"(a1), "r"(a2), "r"(a3), "r"(b0), "r"(b1));
}

#define CP16(dst, src) \
    asm volatile("cp.async.cg.shared.global [%0], [%1], 16;" :: "r"(dst), "l"(src) : "memory")
#define CP_COMMIT() asm volatile("cp.async.commit_group;" ::: "memory")
#define CP_WAIT1()  asm volatile("cp.async.wait_group 1;" ::: "memory")
#define CP_WAIT0()  asm volatile("cp.async.wait_group 0;" ::: "memory")

#define AWORDS 2048
#define BWORDS 2048
#define SMEM_BYTES (3 * (AWORDS + BWORDS) * 4)   // 49152
#define CVTX_SMEM (256 * 132 * 2)                // 67584

// ---------------------------------------------------------------------------
// GEMM machinery: CTA 128x128, 4 warps of 64x64, K stepped by 32 (2 x k16),
// 8 stages, 3-deep cp.async pipeline, fragment-packed fp16 operands.
// Register-lean compute ordering: ks outer (af[4] live), bf transient.
// ---------------------------------------------------------------------------
#define GEMM_ISSUE(S)                                                          \
    do {                                                                       \
        const int _s   = (S);                                                  \
        const int _buf = _s % 3;                                               \
        const uint32_t _aB = smbase + (uint32_t)(_buf * AWORDS) * 4u;          \
        const uint32_t _bB = smbase + (uint32_t)((3 * AWORDS + _buf * BWORDS)) * 4u; \
        _Pragma("unroll")                                                      \
        for (int _i = 0; _i < 4; ++_i) {                                       \
            int _c = tid + (_i << 7);                                          \
            CP16(_aB + (uint32_t)_c * 16u,                                     \
                 gA + ((size_t)(_c >> 6) * 2048 + _s * 256 + (_c & 63) * 4));  \
            CP16(_bB + (uint32_t)_c * 16u,                                     \
                 gB + ((size_t)(_c >> 5) * 1024 + _s * 128 + (_c & 31) * 4));  \
        }                                                                      \
        CP_COMMIT();                                                           \
    } while (0)

#define GEMM_COMPUTE(BUF)                                                      \
    do {                                                                       \
        const uint32_t* _A = dsm + (BUF) * AWORDS;                             \
        const uint32_t* _B = dsm + 3 * AWORDS + (BUF) * BWORDS;                \
        _Pragma("unroll")                                                      \
        for (int ks = 0; ks < 2; ++ks) {                                       \
            uint4 af[4];                                                       \
            _Pragma("unroll")                                                  \
            for (int mt = 0; mt < 4; ++mt)                                     \
                af[mt] = *(const uint4*)(_A + (((wm * 4 + mt) * 2 + ks) << 7)  \
                                              + (lane << 2));                  \
            _Pragma("unroll")                                                  \
            for (int nt = 0; nt < 8; ++nt) {                                   \
                uint4 bf = *(const uint4*)(_B + ((wn * 8 + nt) << 7)           \
                                              + (lane << 2));                  \
                uint32_t b0 = ks ? bf.z : bf.x;                                \
                uint32_t b1 = ks ? bf.w : bf.y;                                \
                _Pragma("unroll")                                              \
                for (int mt = 0; mt < 4; ++mt)                                 \
                    mma16(acc[mt][nt], af[mt].x, af[mt].y, af[mt].z, af[mt].w, \
                          b0, b1);                                             \
            }                                                                  \
        }                                                                      \
    } while (0)

#define GEMM_PROLOG_AND_MAINLOOP()                                             \
    float acc[4][8][4];                                                        \
    _Pragma("unroll")                                                          \
    for (int mt = 0; mt < 4; ++mt)                                             \
        _Pragma("unroll")                                                      \
        for (int nt = 0; nt < 8; ++nt)                                         \
            _Pragma("unroll")                                                  \
            for (int r = 0; r < 4; ++r) acc[mt][nt][r] = 0.f;                  \
    GEMM_ISSUE(0);                                                             \
    GEMM_ISSUE(1);                                                             \
    _Pragma("unroll 1")                                                        \
    for (int s = 0; s < 8; ++s) {                                              \
        if (s < 7) { CP_WAIT1(); } else { CP_WAIT0(); }                        \
        __syncthreads();                                                       \
        if (s < 6) GEMM_ISSUE(s + 2);                                          \
        GEMM_COMPUTE(s % 3);                                                   \
    }

// ---------------------------------------------------------------------------
// GEMM 1: qkv = qkv_w @ x + qkv_b; epilogue packs fp16 Q/K/V fragments.
// ---------------------------------------------------------------------------
__global__ __launch_bounds__(128, 3) void qkv_mma(const float* __restrict__ bias)
{
    extern __shared__ uint32_t dsm[];
    const uint32_t smbase = smem_u32(dsm);

    const int tid  = threadIdx.x;
    const int lane = tid & 31;
    const int wid  = tid >> 5;
    const int g    = lane >> 2;
    const int t4   = lane & 3;
    const int wm   = wid >> 1;
    const int wn   = wid & 1;

    const int gy = blockIdx.y;
    const int b  = gy >> 9;
    const int tl = gy & 511;
    const int w0 = tl << 1;

    const uint32_t* gA = h_wq + (size_t)blockIdx.x * 8 * 2048;
    const uint32_t* gB = h_x + (size_t)b * 8388608 + (size_t)tl * 16384;

    GEMM_PROLOG_AND_MAINLOOP();

    const int g64  = 2 * blockIdx.x + wm;
    const int head = g64 / 3;
    const int typ  = g64 % 3;
    const size_t ubase = (size_t)((b * 4 + head) * 1024 + w0 + wn) * 2048;
    const int e  = g & 1;
    const int pj = g >> 1;

    if (typ == 0) {
        uint32_t* gout = h_qkv + ubase;
#pragma unroll
        for (int mt = 0; mt < 4; ++mt)
#pragma unroll
            for (int half = 0; half < 2; ++half) {
                const float bv = bias[g64 * 64 + mt * 16 + 8 * half + g];
#pragma unroll
                for (int nt = 0; nt < 8; ++nt) {
                    float v0 = 0.125f * (acc[mt][nt][2 * half + 0] + bv);
                    float v1 = 0.125f * (acc[mt][nt][2 * half + 1] + bv);
                    float p0 = __shfl_xor_sync(0xffffffffu, v0, 4);
                    float p1 = __shfl_xor_sync(0xffffffffu, v1, 4);
                    float lo = e ? p1 : v0;
                    float hi = e ? v1 : p0;
                    int word = (nt >> 1) * 512 + mt * 128
                               + ((2 * t4 + e) * 4 + pj) * 4 + half * 2 + (nt & 1);
                    gout[word] = h2(lo, hi);
                }
            }
    } else if (typ == 1) {
        uint32_t* gout = h_qkv + KOFF + ubase;
#pragma unroll
        for (int mt = 0; mt < 4; ++mt)
#pragma unroll
            for (int half = 0; half < 2; ++half) {
                const float bv = bias[g64 * 64 + mt * 16 + 8 * half + g];
#pragma unroll
                for (int nt = 0; nt < 8; ++nt) {
                    float v0 = acc[mt][nt][2 * half + 0] + bv;
                    float v1 = acc[mt][nt][2 * half + 1] + bv;
                    float p0 = __shfl_xor_sync(0xffffffffu, v0, 4);
                    float p1 = __shfl_xor_sync(0xffffffffu, v1, 4);
                    float lo = e ? p1 : v0;
                    float hi = e ? v1 : p0;
                    int word = (nt * 2 + (mt >> 1)) * 128
                               + ((2 * t4 + e) * 4 + pj) * 4 + (mt & 1) * 2 + half;
                    gout[word] = h2(lo, hi);
                }
            }
    } else {
        uint32_t* gout = h_qkv + VOFF + ubase;
#pragma unroll
        for (int mt = 0; mt < 4; ++mt)
#pragma unroll
            for (int half = 0; half < 2; ++half) {
                const float bv = bias[g64 * 64 + mt * 16 + 8 * half + g];
#pragma unroll
                for (int nt = 0; nt < 8; ++nt) {
                    float v0 = acc[mt][nt][2 * half + 0] + bv;
                    float v1 = acc[mt][nt][2 * half + 1] + bv;
                    int word = ((mt * 2 + half) * 2 + (nt >> 2)) * 128
                               + (g * 4 + t4) * 4 + ((nt >> 1) & 1) * 2 + (nt & 1);
                    gout[word] = h2(v0, v1);
                }
            }
    }
}

// ---------------------------------------------------------------------------
// GEMM 2: out = proj_w @ attn + proj_b  (fp32 raster scatter epilogue)
// ---------------------------------------------------------------------------
__global__ __launch_bounds__(128, 3) void proj_mma(const float* __restrict__ bias,
                                                   float* __restrict__ out)
{
    extern __shared__ uint32_t dsm[];
    const uint32_t smbase = smem_u32(dsm);

    const int tid  = threadIdx.x;
    const int lane = tid & 31;
    const int wid  = tid >> 5;
    const int g    = lane >> 2;
    const int t4   = lane & 3;
    const int wm   = wid >> 1;
    const int wn   = wid & 1;

    const int m0 = blockIdx.x << 7;
    const int gy = blockIdx.y;
    const int b  = gy >> 9;
    const int tl = gy & 511;
    const int w0 = tl << 1;

    const uint32_t* gA = h_wp + (size_t)blockIdx.x * 8 * 2048;
    const uint32_t* gB = h_attn + (size_t)b * 8388608 + (size_t)tl * 16384;

    GEMM_PROLOG_AND_MAINLOOP();

#pragma unroll
    for (int mt = 0; mt < 4; ++mt) {
#pragma unroll
        for (int half = 0; half < 2; ++half) {
            const int o = m0 + wm * 64 + mt * 16 + g + half * 8;
            const float bv = bias[o];
            float* obase = out + ((size_t)b * 256 + o) * HW;
#pragma unroll
            for (int nt = 0; nt < 8; ++nt) {
                const int col = wn * 64 + nt * 8 + 2 * t4;
                const int win = w0 + (col >> 6);
                const int t64 = col & 63;
                const int y   = ((win >> 5) << 3) + (t64 >> 3);
                const int xx  = ((win & 31) << 3) + (t64 & 7);
                float2 ov = make_float2(acc[mt][nt][2 * half] + bv,
                                        acc[mt][nt][2 * half + 1] + bv);
                *(float2*)(obase + y * IMW + xx) = ov;
            }
        }
    }
}

// ---------------------------------------------------------------------------
// Prepass: fp16-round weights into A-fragment-packed layout.
// ---------------------------------------------------------------------------
__global__ __launch_bounds__(256) void cvt_weights(const float* __restrict__ qw,
                                                   const float* __restrict__ pw)
{
    int i = blockIdx.x * 256 + threadIdx.x;
    if (i < 196608) {
        int o = i >> 8, c = i & 255;
        int word = (o >> 4) * 2048 + (c >> 4) * 128
                   + ((o & 7) * 4 + (((c & 15) & 7) >> 1)) * 4
                   + ((c >> 3) & 1) * 2 + ((o >> 3) & 1);
        ((__half*)h_wq)[word * 2 + (c & 1)] = __float2half_rn(qw[i]);
    }
    if (i < 65536) {
        int o = i >> 8, c = i & 255;
        int word = (o >> 4) * 2048 + (c >> 4) * 128
                   + ((o & 7) * 4 + (((c & 15) & 7) >> 1)) * 4
                   + ((c >> 3) & 1) * 2 + ((o >> 3) & 1);
        ((__half*)h_wp)[word * 2 + (c & 1)] = __float2half_rn(pw[i]);
    }
}

// ---------------------------------------------------------------------------
// Prepass: fp16 + window-major + B-fragment-pack x via smem transpose.
// ---------------------------------------------------------------------------
__global__ __launch_bounds__(256) void cvt_x(const float* __restrict__ x)
{
    extern __shared__ __half sh[];   // [256][132]
    const int bt = blockIdx.x;
    const int b  = bt >> 9, tl = bt & 511;
    const int tid = threadIdx.x;
    const int w0 = tl << 1;

#pragma unroll 4
    for (int it = 0; it < 32; ++it) {
        int idx = it * 256 + tid;
        int c = idx >> 5, tq = idx & 31;
        int tok4 = tq << 2;
        int win = w0 + (tok4 >> 6), t64 = tok4 & 63;
        int y = ((win >> 5) << 3) + (t64 >> 3), xx = ((win & 31) << 3) + (t64 & 7);
        float4 v = *(const float4*)(x + ((size_t)(b * 256 + c)) * HW + y * IMW + xx);
        __half2* dst = (__half2*)(sh + c * 132 + tok4);
        dst[0] = __floats2half2_rn(v.x, v.y);
        dst[1] = __floats2half2_rn(v.z, v.w);
    }
    __syncthreads();

    uint32_t* outp = h_x + (size_t)b * 8388608 + (size_t)tl * 16384;
#pragma unroll 4
    for (int it = 0; it < 64; ++it) {
        int widx = it * 256 + tid;
        int t8L = widx >> 10, rest = widx & 1023;
        int s = rest >> 7, lw = rest & 127;
        int lc = lw >> 2, sub = lw & 3;
        int ks = sub >> 1, r = sub & 1;
        int gg = lc >> 2, tt4 = lc & 3;
        int tok = t8L * 8 + gg;
        int c0 = s * 32 + ks * 16 + r * 8 + 2 * tt4;
        outp[widx] = h2(__half2float(sh[c0 * 132 + tok]),
                        __half2float(sh[(c0 + 1) * 132 + tok]));
    }
}

// ---------------------------------------------------------------------------
// fp16 tensor-core window attention: one CTA (4 warps) per (window, head).
// K/V bulk cp.async, Q LDG, P fragments = pure register repack.
// ---------------------------------------------------------------------------
__global__ __launch_bounds__(128) void attn_mma()
{
    __shared__ uint32_t sm[4096];    // K[2048] | V[2048]
    const uint32_t smbase = smem_u32(sm);

    const int tid  = threadIdx.x;
    const int lane = tid & 31;
    const int wrp  = tid >> 5;
    const int g    = lane >> 2;
    const int t4   = lane & 3;

    const int win = blockIdx.x;
    const int hd  = blockIdx.y;
    const int b   = blockIdx.z;

    const size_t unit = (size_t)((b * 4 + hd) * 1024 + win) * 2048;
    const uint32_t* gq = h_qkv + unit;
    const uint32_t* gk = h_qkv + KOFF + unit;
    const uint32_t* gv = h_qkv + VOFF + unit;

#pragma unroll
    for (int i = 0; i < 4; ++i) {
        int c = tid + i * 128;
        CP16(smbase + (uint32_t)c * 16u, gk + (size_t)c * 4);
        CP16(smbase + 8192u + (uint32_t)c * 16u, gv + (size_t)c * 4);
    }
    CP_COMMIT();

    uint4 qf[4];
#pragma unroll
    for (int kc = 0; kc < 4; ++kc)
        qf[kc] = *(const uint4*)(gq + wrp * 512 + kc * 128 + lane * 4);

    CP_WAIT0();
    __syncthreads();

    const uint32_t* ksm = sm;
    const uint32_t* vsm = sm + 2048;

    float acc[8][4];
#pragma unroll
    for (int nt = 0; nt < 8; ++nt)
#pragma unroll
        for (int r = 0; r < 4; ++r) acc[nt][r] = 0.f;

#pragma unroll
    for (int c32 = 0; c32 < 2; ++c32)
#pragma unroll
        for (int nt = 0; nt < 8; ++nt) {
            uint4 kf = *(const uint4*)(ksm + (nt * 2 + c32) * 128 + lane * 4);
            mma16(acc[nt], qf[2 * c32].x, qf[2 * c32].y, qf[2 * c32].z, qf[2 * c32].w,
                  kf.x, kf.y);
            mma16(acc[nt], qf[2 * c32 + 1].x, qf[2 * c32 + 1].y, qf[2 * c32 + 1].z,
                  qf[2 * c32 + 1].w, kf.z, kf.w);
        }

    float mx0 = -1e30f, mx1 = -1e30f;
#pragma unroll
    for (int nt = 0; nt < 8; ++nt) {
        mx0 = fmaxf(mx0, fmaxf(acc[nt][0], acc[nt][1]));
        mx1 = fmaxf(mx1, fmaxf(acc[nt][2], acc[nt][3]));
    }
    mx0 = fmaxf(mx0, __shfl_xor_sync(0xffffffffu, mx0, 1));
    mx0 = fmaxf(mx0, __shfl_xor_sync(0xffffffffu, mx0, 2));
    mx1 = fmaxf(mx1, __shfl_xor_sync(0xffffffffu, mx1, 1));
    mx1 = fmaxf(mx1, __shfl_xor_sync(0xffffffffu, mx1, 2));

    float sm0 = 0.f, sm1 = 0.f;
#pragma unroll
    for (int nt = 0; nt < 8; ++nt) {
        acc[nt][0] = __expf(acc[nt][0] - mx0);
        acc[nt][1] = __expf(acc[nt][1] - mx0);
        acc[nt][2] = __expf(acc[nt][2] - mx1);
        acc[nt][3] = __expf(acc[nt][3] - mx1);
        sm0 += acc[nt][0] + acc[nt][1];
        sm1 += acc[nt][2] + acc[nt][3];
    }
    sm0 += __shfl_xor_sync(0xffffffffu, sm0, 1);
    sm0 += __shfl_xor_sync(0xffffffffu, sm0, 2);
    sm1 += __shfl_xor_sync(0xffffffffu, sm1, 1);
    sm1 += __shfl_xor_sync(0xffffffffu, sm1, 2);
    const float inv0 = 1.0f / sm0;
    const float inv1 = 1.0f / sm1;

    uint32_t pa[4][4];
#pragma unroll
    for (int u = 0; u < 4; ++u) {
        pa[u][0] = h2(acc[2 * u][0],     acc[2 * u][1]);
        pa[u][1] = h2(acc[2 * u][2],     acc[2 * u][3]);
        pa[u][2] = h2(acc[2 * u + 1][0], acc[2 * u + 1][1]);
        pa[u][3] = h2(acc[2 * u + 1][2], acc[2 * u + 1][3]);
    }

    float oac[8][4];
#pragma unroll
    for (int nt = 0; nt < 8; ++nt)
#pragma unroll
        for (int r = 0; r < 4; ++r) oac[nt][r] = 0.f;

#pragma unroll
    for (int uc32 = 0; uc32 < 2; ++uc32)
#pragma unroll
        for (int nt = 0; nt < 8; ++nt) {
            uint4 vf = *(const uint4*)(vsm + (nt * 2 + uc32) * 128 + lane * 4);
            mma16(oac[nt], pa[2 * uc32][0], pa[2 * uc32][1], pa[2 * uc32][2],
                  pa[2 * uc32][3], vf.x, vf.y);
            mma16(oac[nt], pa[2 * uc32 + 1][0], pa[2 * uc32 + 1][1],
                  pa[2 * uc32 + 1][2], pa[2 * uc32 + 1][3], vf.z, vf.w);
        }

    uint32_t* ga = h_attn + (size_t)b * 8388608;
    const int t8b = win * 8 + wrp * 2;
#pragma unroll
    for (int nt = 0; nt < 8; ++nt) {
        const int s  = hd * 2 + (nt >> 2);
        const int ks = (nt >> 1) & 1;
        const int r  = nt & 1;
#pragma unroll
        for (int rh = 0; rh < 2; ++rh) {
            const float inv = rh ? inv1 : inv0;
            int word = (t8b + rh) * 1024 + s * 128 + (g * 4 + t4) * 4 + ks * 2 + r;
            ga[word] = h2(oac[nt][2 * rh] * inv, oac[nt][2 * rh + 1] * inv);
        }
    }
}

// ---------------------------------------------------------------------------
extern "C" void kernel_launch(void* const* d_in, const int* in_sizes, int n_in,
                              void* d_out, int out_size)
{
    (void)in_sizes; (void)n_in; (void)out_size;
    const float* x      = (const float*)d_in[0];
    const float* qkv_w  = (const float*)d_in[1];
    const float* qkv_b  = (const float*)d_in[2];
    const float* proj_w = (const float*)d_in[3];
    const float* proj_b = (const float*)d_in[4];
    float* out = (float*)d_out;

    static int attr_done = 0;
    if (!attr_done) {
        cudaFuncSetAttribute(qkv_mma,  cudaFuncAttributeMaxDynamicSharedMemorySize, SMEM_BYTES);
        cudaFuncSetAttribute(proj_mma, cudaFuncAttributeMaxDynamicSharedMemorySize, SMEM_BYTES);
        cudaFuncSetAttribute(cvt_x,    cudaFuncAttributeMaxDynamicSharedMemorySize, CVTX_SMEM);
        attr_done = 1;
    }

    cvt_weights<<<768, 256>>>(qkv_w, proj_w);
    cvt_x<<<4096, 256, CVTX_SMEM>>>(x);
    qkv_mma<<<dim3(6, 4096), 128, SMEM_BYTES>>>(qkv_b);
    attn_mma<<<dim3(1024, 4, 8), 128>>>();
    proj_mma<<<dim3(2, 4096), 128, SMEM_BYTES>>>(proj_b, out);
}

// round 12
// speedup vs baseline: 1.1644x; 1.1644x over previous
#include <cuda_runtime.h>
#include <cuda_fp16.h>
#include <math.h>
#include <stdint.h>

// Problem constants: B=8, C=256, H=W=256, WS=8, HEADS=4, dh=64
#define HW  65536
#define IMW 256

// fp16 fragment-packed scratch (all m16n8k16 layouts), stored as u32 (half2):
//  h_qkv: Q | K | V regions, 2048 words per (b,hd,win) unit.
//  h_x / h_attn (GEMM B): [b][t8 8192][s 8][lane*4 + ks*2 + r] (pairs over chan)
//  h_wq / h_wp (GEMM A): [mt][k16 16][lane*4 + hik*2 + him]
__device__ uint32_t h_qkv[201326592];
__device__ uint32_t h_x[67108864];
__device__ uint32_t h_attn[67108864];
__device__ uint32_t h_wq[98304];
__device__ uint32_t h_wp[32768];

#define KOFF 67108864
#define VOFF 134217728

__device__ __forceinline__ uint32_t smem_u32(const void* p) {
    uint32_t a;
    asm("{ .reg .u64 t; cvta.to.shared.u64 t, %1; cvt.u32.u64 %0, t; }" : "=r"(a) : "l"(p));
    return a;
}

__device__ __forceinline__ uint32_t h2(float lo, float hi) {
    __half2 h = __floats2half2_rn(lo, hi);
    return *(uint32_t*)&h;
}

__device__ __forceinline__ void mma16(float c[4],
                                      uint32_t a0, uint32_t a1, uint32_t a2, uint32_t a3,
                                      uint32_t b0, uint32_t b1) {
    asm volatile(
        "mma.sync.aligned.m16n8k16.row.col.f32.f16.f16.f32 "
        "{%0,%1,%2,%3}, {%4,%5,%6,%7}, {%8,%9}, {%0,%1,%2,%3};"
        : "+f"(c[0]), "+f"(c[1]), "+f"(c[2]), "+f"(c[3])
        : "r"(a0), "r"(a1), "r"(a2), "r"(a3), "r"(b0), "r"(b1));
}

#define CP16(dst, src) \
    asm volatile("cp.async.cg.shared.global [%0], [%1], 16;" :: "r"(dst), "l"(src) : "memory")
#define CP_COMMIT() asm volatile("cp.async.commit_group;" ::: "memory")
#define CP_WAIT1()  asm volatile("cp.async.wait_group 1;" ::: "memory")
#define CP_WAIT0()  asm volatile("cp.async.wait_group 0;" ::: "memory")

#define AWORDS 2048
#define BWORDS 2048
#define SMEM_BYTES (3 * (AWORDS + BWORDS) * 4)   // 49152 (proj)
// qkv: A 3 stages x 2048 + resident B 16384 words = 22528 words
#define QKV_SMEM_BYTES (22528 * 4)               // 90112
#define CVTX_SMEM (256 * 132 * 2)                // 67584

// ---------------------------------------------------------------------------
// Round-8 GEMM machinery (used by proj): CTA 128x128, 4 warps of 64x64,
// K stepped by 32 (2 x k16), 8 stages, 3-deep cp.async pipeline.
// ---------------------------------------------------------------------------
#define GEMM_ISSUE(S)                                                          \
    do {                                                                       \
        const int _s   = (S);                                                  \
        const int _buf = _s % 3;                                               \
        const uint32_t _aB = smbase + (uint32_t)(_buf * AWORDS) * 4u;          \
        const uint32_t _bB = smbase + (uint32_t)((3 * AWORDS + _buf * BWORDS)) * 4u; \
        _Pragma("unroll")                                                      \
        for (int _i = 0; _i < 4; ++_i) {                                       \
            int _c = tid + (_i << 7);                                          \
            CP16(_aB + (uint32_t)_c * 16u,                                     \
                 gA + ((size_t)(_c >> 6) * 2048 + _s * 256 + (_c & 63) * 4));  \
            CP16(_bB + (uint32_t)_c * 16u,                                     \
                 gB + ((size_t)(_c >> 5) * 1024 + _s * 128 + (_c & 31) * 4));  \
        }                                                                      \
        CP_COMMIT();                                                           \
    } while (0)

#define GEMM_COMPUTE(BUF)                                                      \
    do {                                                                       \
        const uint32_t* _A = dsm + (BUF) * AWORDS;                             \
        const uint32_t* _B = dsm + 3 * AWORDS + (BUF) * BWORDS;                \
        uint4 bf[8];                                                           \
        _Pragma("unroll")                                                      \
        for (int nt = 0; nt < 8; ++nt)                                         \
            bf[nt] = *(const uint4*)(_B + ((wn * 8 + nt) << 7) + (lane << 2)); \
        _Pragma("unroll")                                                      \
        for (int ks = 0; ks < 2; ++ks) {                                       \
            uint4 af[4];                                                       \
            _Pragma("unroll")                                                  \
            for (int mt = 0; mt < 4; ++mt)                                     \
                af[mt] = *(const uint4*)(_A + (((wm * 4 + mt) * 2 + ks) << 7)  \
                                              + (lane << 2));                  \
            _Pragma("unroll")                                                  \
            for (int mt = 0; mt < 4; ++mt)                                     \
                _Pragma("unroll")                                              \
                for (int nt = 0; nt < 8; ++nt)                                 \
                    mma16(acc[mt][nt], af[mt].x, af[mt].y, af[mt].z, af[mt].w, \
                          ks ? bf[nt].z : bf[nt].x, ks ? bf[nt].w : bf[nt].y); \
        }                                                                      \
    } while (0)

// ---------------------------------------------------------------------------
// GEMM 1 (B-resident): one CTA owns ALL 768 out-channels for its 128 tokens.
// B (64KB) staged once; A streamed through a flat 48-stage cp.async chain.
// Epilogue per 128-channel M-tile packs fp16 Q/K/V fragments (Round-8 code).
// ---------------------------------------------------------------------------
__global__ __launch_bounds__(128) void qkv_mma(const float* __restrict__ bias)
{
    extern __shared__ uint32_t dsm[];
    const uint32_t smbase = smem_u32(dsm);

    const int tid  = threadIdx.x;
    const int lane = tid & 31;
    const int wid  = tid >> 5;
    const int g    = lane >> 2;
    const int t4   = lane & 3;
    const int wm   = wid >> 1;
    const int wn   = wid & 1;

    const int gy = blockIdx.x;
    const int b  = gy >> 9;
    const int tl = gy & 511;
    const int w0 = tl << 1;

    const uint32_t* gB = h_x + (size_t)b * 8388608 + (size_t)tl * 16384;

    // Stage resident B (64KB) as cp.async group 0.
#pragma unroll
    for (int i = 0; i < 32; ++i) {
        int c = tid + (i << 7);
        CP16(smbase + (uint32_t)(6144 + c * 4) * 4u, gB + (size_t)c * 4);
    }
    CP_COMMIT();

    // A stage issue: global stage gs in [0,48); buffer gs%3.
#define QISSUE(GS)                                                             \
    do {                                                                       \
        const int _gs = (GS);                                                  \
        const uint32_t _aB = smbase + (uint32_t)((_gs % 3) * AWORDS) * 4u;     \
        const uint32_t* _gA = h_wq + (size_t)(_gs >> 3) * 16384;               \
        _Pragma("unroll")                                                      \
        for (int _i = 0; _i < 4; ++_i) {                                       \
            int _c = tid + (_i << 7);                                          \
            CP16(_aB + (uint32_t)_c * 16u,                                     \
                 _gA + ((size_t)(_c >> 6) * 2048 + (_gs & 7) * 256             \
                        + (_c & 63) * 4));                                     \
        }                                                                      \
        CP_COMMIT();                                                           \
    } while (0)

    QISSUE(0);
    QISSUE(1);

    const int e  = g & 1;
    const int pj = g >> 1;

#pragma unroll 1
    for (int m = 0; m < 6; ++m) {
        float acc[4][8][4];
#pragma unroll
        for (int mt = 0; mt < 4; ++mt)
#pragma unroll
            for (int nt = 0; nt < 8; ++nt)
#pragma unroll
                for (int r = 0; r < 4; ++r) acc[mt][nt][r] = 0.f;

#pragma unroll 1
        for (int s = 0; s < 8; ++s) {
            const int gs = m * 8 + s;
            if (gs < 47) { CP_WAIT1(); } else { CP_WAIT0(); }
            __syncthreads();
            if (gs + 2 < 48) QISSUE(gs + 2);

            const uint32_t* _A = dsm + (gs % 3) * AWORDS;
            const uint32_t* _B = dsm + 6144;
            uint4 bf[8];
#pragma unroll
            for (int nt = 0; nt < 8; ++nt)
                bf[nt] = *(const uint4*)(_B + (wn * 8 + nt) * 1024 + s * 128
                                              + (lane << 2));
#pragma unroll
            for (int ks = 0; ks < 2; ++ks) {
                uint4 af[4];
#pragma unroll
                for (int mt = 0; mt < 4; ++mt)
                    af[mt] = *(const uint4*)(_A + (((wm * 4 + mt) * 2 + ks) << 7)
                                                  + (lane << 2));
#pragma unroll
                for (int mt = 0; mt < 4; ++mt)
#pragma unroll
                    for (int nt = 0; nt < 8; ++nt)
                        mma16(acc[mt][nt], af[mt].x, af[mt].y, af[mt].z, af[mt].w,
                              ks ? bf[nt].z : bf[nt].x, ks ? bf[nt].w : bf[nt].y);
            }
        }

        // Epilogue for M-tile m (identical math to Round 8, blockIdx.x -> m)
        const int g64  = 2 * m + wm;
        const int head = g64 / 3;
        const int typ  = g64 % 3;
        const size_t ubase = (size_t)((b * 4 + head) * 1024 + w0 + wn) * 2048;

        if (typ == 0) {
            uint32_t* gout = h_qkv + ubase;
#pragma unroll
            for (int mt = 0; mt < 4; ++mt)
#pragma unroll
                for (int half = 0; half < 2; ++half) {
                    const float bv = bias[g64 * 64 + mt * 16 + 8 * half + g];
#pragma unroll
                    for (int nt = 0; nt < 8; ++nt) {
                        float v0 = 0.125f * (acc[mt][nt][2 * half + 0] + bv);
                        float v1 = 0.125f * (acc[mt][nt][2 * half + 1] + bv);
                        float p0 = __shfl_xor_sync(0xffffffffu, v0, 4);
                        float p1 = __shfl_xor_sync(0xffffffffu, v1, 4);
                        float lo = e ? p1 : v0;
                        float hi = e ? v1 : p0;
                        int word = (nt >> 1) * 512 + mt * 128
                                   + ((2 * t4 + e) * 4 + pj) * 4 + half * 2 + (nt & 1);
                        gout[word] = h2(lo, hi);
                    }
                }
        } else if (typ == 1) {
            uint32_t* gout = h_qkv + KOFF + ubase;
#pragma unroll
            for (int mt = 0; mt < 4; ++mt)
#pragma unroll
                for (int half = 0; half < 2; ++half) {
                    const float bv = bias[g64 * 64 + mt * 16 + 8 * half + g];
#pragma unroll
                    for (int nt = 0; nt < 8; ++nt) {
                        float v0 = acc[mt][nt][2 * half + 0] + bv;
                        float v1 = acc[mt][nt][2 * half + 1] + bv;
                        float p0 = __shfl_xor_sync(0xffffffffu, v0, 4);
                        float p1 = __shfl_xor_sync(0xffffffffu, v1, 4);
                        float lo = e ? p1 : v0;
                        float hi = e ? v1 : p0;
                        int word = (nt * 2 + (mt >> 1)) * 128
                                   + ((2 * t4 + e) * 4 + pj) * 4 + (mt & 1) * 2 + half;
                        gout[word] = h2(lo, hi);
                    }
                }
        } else {
            uint32_t* gout = h_qkv + VOFF + ubase;
#pragma unroll
            for (int mt = 0; mt < 4; ++mt)
#pragma unroll
                for (int half = 0; half < 2; ++half) {
                    const float bv = bias[g64 * 64 + mt * 16 + 8 * half + g];
#pragma unroll
                    for (int nt = 0; nt < 8; ++nt) {
                        float v0 = acc[mt][nt][2 * half + 0] + bv;
                        float v1 = acc[mt][nt][2 * half + 1] + bv;
                        int word = ((mt * 2 + half) * 2 + (nt >> 2)) * 128
                                   + (g * 4 + t4) * 4 + ((nt >> 1) & 1) * 2 + (nt & 1);
                        gout[word] = h2(v0, v1);
                    }
                }
        }
    }
#undef QISSUE
}

// ---------------------------------------------------------------------------
// GEMM 2: out = proj_w @ attn + proj_b  (Round-8 exact)
// ---------------------------------------------------------------------------
__global__ __launch_bounds__(128) void proj_mma(const float* __restrict__ bias,
                                                float* __restrict__ out)
{
    extern __shared__ uint32_t dsm[];
    const uint32_t smbase = smem_u32(dsm);

    const int tid  = threadIdx.x;
    const int lane = tid & 31;
    const int wid  = tid >> 5;
    const int g    = lane >> 2;
    const int t4   = lane & 3;
    const int wm   = wid >> 1;
    const int wn   = wid & 1;

    const int m0 = blockIdx.x << 7;
    const int gy = blockIdx.y;
    const int b  = gy >> 9;
    const int tl = gy & 511;
    const int w0 = tl << 1;

    const uint32_t* gA = h_wp + (size_t)blockIdx.x * 8 * 2048;
    const uint32_t* gB = h_attn + (size_t)b * 8388608 + (size_t)tl * 16384;

    float acc[4][8][4];
#pragma unroll
    for (int mt = 0; mt < 4; ++mt)
#pragma unroll
        for (int nt = 0; nt < 8; ++nt)
#pragma unroll
            for (int r = 0; r < 4; ++r) acc[mt][nt][r] = 0.f;

    GEMM_ISSUE(0);
    GEMM_ISSUE(1);
#pragma unroll 1
    for (int s = 0; s < 8; ++s) {
        if (s < 7) { CP_WAIT1(); } else { CP_WAIT0(); }
        __syncthreads();
        if (s < 6) GEMM_ISSUE(s + 2);
        GEMM_COMPUTE(s % 3);
    }

#pragma unroll
    for (int mt = 0; mt < 4; ++mt) {
#pragma unroll
        for (int half = 0; half < 2; ++half) {
            const int o = m0 + wm * 64 + mt * 16 + g + half * 8;
            const float bv = bias[o];
            float* obase = out + ((size_t)b * 256 + o) * HW;
#pragma unroll
            for (int nt = 0; nt < 8; ++nt) {
                const int col = wn * 64 + nt * 8 + 2 * t4;
                const int win = w0 + (col >> 6);
                const int t64 = col & 63;
                const int y   = ((win >> 5) << 3) + (t64 >> 3);
                const int xx  = ((win & 31) << 3) + (t64 & 7);
                float2 ov = make_float2(acc[mt][nt][2 * half] + bv,
                                        acc[mt][nt][2 * half + 1] + bv);
                *(float2*)(obase + y * IMW + xx) = ov;
            }
        }
    }
}

// ---------------------------------------------------------------------------
// Prepass: fp16-round weights into A-fragment-packed layout.
// ---------------------------------------------------------------------------
__global__ __launch_bounds__(256) void cvt_weights(const float* __restrict__ qw,
                                                   const float* __restrict__ pw)
{
    int i = blockIdx.x * 256 + threadIdx.x;
    if (i < 196608) {
        int o = i >> 8, c = i & 255;
        int word = (o >> 4) * 2048 + (c >> 4) * 128
                   + ((o & 7) * 4 + (((c & 15) & 7) >> 1)) * 4
                   + ((c >> 3) & 1) * 2 + ((o >> 3) & 1);
        ((__half*)h_wq)[word * 2 + (c & 1)] = __float2half_rn(qw[i]);
    }
    if (i < 65536) {
        int o = i >> 8, c = i & 255;
        int word = (o >> 4) * 2048 + (c >> 4) * 128
                   + ((o & 7) * 4 + (((c & 15) & 7) >> 1)) * 4
                   + ((c >> 3) & 1) * 2 + ((o >> 3) & 1);
        ((__half*)h_wp)[word * 2 + (c & 1)] = __float2half_rn(pw[i]);
    }
}

// ---------------------------------------------------------------------------
// Prepass: fp16 + window-major + B-fragment-pack x via smem transpose.
// ---------------------------------------------------------------------------
__global__ __launch_bounds__(256) void cvt_x(const float* __restrict__ x)
{
    extern __shared__ __half sh[];   // [256][132]
    const int bt = blockIdx.x;
    const int b  = bt >> 9, tl = bt & 511;
    const int tid = threadIdx.x;
    const int w0 = tl << 1;

#pragma unroll 4
    for (int it = 0; it < 32; ++it) {
        int idx = it * 256 + tid;
        int c = idx >> 5, tq = idx & 31;
        int tok4 = tq << 2;
        int win = w0 + (tok4 >> 6), t64 = tok4 & 63;
        int y = ((win >> 5) << 3) + (t64 >> 3), xx = ((win & 31) << 3) + (t64 & 7);
        float4 v = *(const float4*)(x + ((size_t)(b * 256 + c)) * HW + y * IMW + xx);
        __half2* dst = (__half2*)(sh + c * 132 + tok4);
        dst[0] = __floats2half2_rn(v.x, v.y);
        dst[1] = __floats2half2_rn(v.z, v.w);
    }
    __syncthreads();

    uint32_t* outp = h_x + (size_t)b * 8388608 + (size_t)tl * 16384;
#pragma unroll 4
    for (int it = 0; it < 64; ++it) {
        int widx = it * 256 + tid;
        int t8L = widx >> 10, rest = widx & 1023;
        int s = rest >> 7, lw = rest & 127;
        int lc = lw >> 2, sub = lw & 3;
        int ks = sub >> 1, r = sub & 1;
        int gg = lc >> 2, tt4 = lc & 3;
        int tok = t8L * 8 + gg;
        int c0 = s * 32 + ks * 16 + r * 8 + 2 * tt4;
        outp[widx] = h2(__half2float(sh[c0 * 132 + tok]),
                        __half2float(sh[(c0 + 1) * 132 + tok]));
    }
}

// ---------------------------------------------------------------------------
// fp16 tensor-core window attention (Round-8 exact).
// ---------------------------------------------------------------------------
__global__ __launch_bounds__(128) void attn_mma()
{
    __shared__ uint32_t sm[4096];    // K[2048] | V[2048]
    const uint32_t smbase = smem_u32(sm);

    const int tid  = threadIdx.x;
    const int lane = tid & 31;
    const int wrp  = tid >> 5;
    const int g    = lane >> 2;
    const int t4   = lane & 3;

    const int win = blockIdx.x;
    const int hd  = blockIdx.y;
    const int b   = blockIdx.z;

    const size_t unit = (size_t)((b * 4 + hd) * 1024 + win) * 2048;
    const uint32_t* gq = h_qkv + unit;
    const uint32_t* gk = h_qkv + KOFF + unit;
    const uint32_t* gv = h_qkv + VOFF + unit;

#pragma unroll
    for (int i = 0; i < 4; ++i) {
        int c = tid + i * 128;
        CP16(smbase + (uint32_t)c * 16u, gk + (size_t)c * 4);
        CP16(smbase + 8192u + (uint32_t)c * 16u, gv + (size_t)c * 4);
    }
    CP_COMMIT();

    uint4 qf[4];
#pragma unroll
    for (int kc = 0; kc < 4; ++kc)
        qf[kc] = *(const uint4*)(gq + wrp * 512 + kc * 128 + lane * 4);

    CP_WAIT0();
    __syncthreads();

    const uint32_t* ksm = sm;
    const uint32_t* vsm = sm + 2048;

    float acc[8][4];
#pragma unroll
    for (int nt = 0; nt < 8; ++nt)
#pragma unroll
        for (int r = 0; r < 4; ++r) acc[nt][r] = 0.f;

#pragma unroll
    for (int c32 = 0; c32 < 2; ++c32)
#pragma unroll
        for (int nt = 0; nt < 8; ++nt) {
            uint4 kf = *(const uint4*)(ksm + (nt * 2 + c32) * 128 + lane * 4);
            mma16(acc[nt], qf[2 * c32].x, qf[2 * c32].y, qf[2 * c32].z, qf[2 * c32].w,
                  kf.x, kf.y);
            mma16(acc[nt], qf[2 * c32 + 1].x, qf[2 * c32 + 1].y, qf[2 * c32 + 1].z,
                  qf[2 * c32 + 1].w, kf.z, kf.w);
        }

    float mx0 = -1e30f, mx1 = -1e30f;
#pragma unroll
    for (int nt = 0; nt < 8; ++nt) {
        mx0 = fmaxf(mx0, fmaxf(acc[nt][0], acc[nt][1]));
        mx1 = fmaxf(mx1, fmaxf(acc[nt][2], acc[nt][3]));
    }
    mx0 = fmaxf(mx0, __shfl_xor_sync(0xffffffffu, mx0, 1));
    mx0 = fmaxf(mx0, __shfl_xor_sync(0xffffffffu, mx0, 2));
    mx1 = fmaxf(mx1, __shfl_xor_sync(0xffffffffu, mx1, 1));
    mx1 = fmaxf(mx1, __shfl_xor_sync(0xffffffffu, mx1, 2));

    float sm0 = 0.f, sm1 = 0.f;
#pragma unroll
    for (int nt = 0; nt < 8; ++nt) {
        acc[nt][0] = __expf(acc[nt][0] - mx0);
        acc[nt][1] = __expf(acc[nt][1] - mx0);
        acc[nt][2] = __expf(acc[nt][2] - mx1);
        acc[nt][3] = __expf(acc[nt][3] - mx1);
        sm0 += acc[nt][0] + acc[nt][1];
        sm1 += acc[nt][2] + acc[nt][3];
    }
    sm0 += __shfl_xor_sync(0xffffffffu, sm0, 1);
    sm0 += __shfl_xor_sync(0xffffffffu, sm0, 2);
    sm1 += __shfl_xor_sync(0xffffffffu, sm1, 1);
    sm1 += __shfl_xor_sync(0xffffffffu, sm1, 2);
    const float inv0 = 1.0f / sm0;
    const float inv1 = 1.0f / sm1;

    uint32_t pa[4][4];
#pragma unroll
    for (int u = 0; u < 4; ++u) {
        pa[u][0] = h2(acc[2 * u][0],     acc[2 * u][1]);
        pa[u][1] = h2(acc[2 * u][2],     acc[2 * u][3]);
        pa[u][2] = h2(acc[2 * u + 1][0], acc[2 * u + 1][1]);
        pa[u][3] = h2(acc[2 * u + 1][2], acc[2 * u + 1][3]);
    }

    float oac[8][4];
#pragma unroll
    for (int nt = 0; nt < 8; ++nt)
#pragma unroll
        for (int r = 0; r < 4; ++r) oac[nt][r] = 0.f;

#pragma unroll
    for (int uc32 = 0; uc32 < 2; ++uc32)
#pragma unroll
        for (int nt = 0; nt < 8; ++nt) {
            uint4 vf = *(const uint4*)(vsm + (nt * 2 + uc32) * 128 + lane * 4);
            mma16(oac[nt], pa[2 * uc32][0], pa[2 * uc32][1], pa[2 * uc32][2],
                  pa[2 * uc32][3], vf.x, vf.y);
            mma16(oac[nt], pa[2 * uc32 + 1][0], pa[2 * uc32 + 1][1],
                  pa[2 * uc32 + 1][2], pa[2 * uc32 + 1][3], vf.z, vf.w);
        }

    uint32_t* ga = h_attn + (size_t)b * 8388608;
    const int t8b = win * 8 + wrp * 2;
#pragma unroll
    for (int nt = 0; nt < 8; ++nt) {
        const int s  = hd * 2 + (nt >> 2);
        const int ks = (nt >> 1) & 1;
        const int r  = nt & 1;
#pragma unroll
        for (int rh = 0; rh < 2; ++rh) {
            const float inv = rh ? inv1 : inv0;
            int word = (t8b + rh) * 1024 + s * 128 + (g * 4 + t4) * 4 + ks * 2 + r;
            ga[word] = h2(oac[nt][2 * rh] * inv, oac[nt][2 * rh + 1] * inv);
        }
    }
}

// ---------------------------------------------------------------------------
extern "C" void kernel_launch(void* const* d_in, const int* in_sizes, int n_in,
                              void* d_out, int out_size)
{
    (void)in_sizes; (void)n_in; (void)out_size;
    const float* x      = (const float*)d_in[0];
    const float* qkv_w  = (const float*)d_in[1];
    const float* qkv_b  = (const float*)d_in[2];
    const float* proj_w = (const float*)d_in[3];
    const float* proj_b = (const float*)d_in[4];
    float* out = (float*)d_out;

    static int attr_done = 0;
    if (!attr_done) {
        cudaFuncSetAttribute(qkv_mma,  cudaFuncAttributeMaxDynamicSharedMemorySize, QKV_SMEM_BYTES);
        cudaFuncSetAttribute(proj_mma, cudaFuncAttributeMaxDynamicSharedMemorySize, SMEM_BYTES);
        cudaFuncSetAttribute(cvt_x,    cudaFuncAttributeMaxDynamicSharedMemorySize, CVTX_SMEM);
        attr_done = 1;
    }

    cvt_weights<<<768, 256>>>(qkv_w, proj_w);
    cvt_x<<<4096, 256, CVTX_SMEM>>>(x);
    qkv_mma<<<4096, 128, QKV_SMEM_BYTES>>>(qkv_b);
    attn_mma<<<dim3(1024, 4, 8), 128>>>();
    proj_mma<<<dim3(2, 4096), 128, SMEM_BYTES>>>(proj_b, out);
}

// round 14
// speedup vs baseline: 1.1965x; 1.0275x over previous
#include <cuda_runtime.h>
#include <cuda_fp16.h>
#include <math.h>
#include <stdint.h>

// Problem constants: B=8, C=256, H=W=256, WS=8, HEADS=4, dh=64
#define HW  65536
#define IMW 256

// fp16 fragment-packed scratch (all m16n8k16 layouts), stored as u32 (half2):
//  h_qkv: Q | K | V regions, 2048 words per (b,hd,win) unit.
//  h_x / h_attn (GEMM B): [b][t8 8192][s 8][lane*4 + ks*2 + r] (pairs over chan)
//  h_wq / h_wp (GEMM A): [mt][k16 16][lane*4 + hik*2 + him]
__device__ uint32_t h_qkv[201326592];
__device__ uint32_t h_x[67108864];
__device__ uint32_t h_attn[67108864];
__device__ uint32_t h_wq[98304];
__device__ uint32_t h_wp[32768];

#define KOFF 67108864
#define VOFF 134217728

__device__ __forceinline__ uint32_t smem_u32(const void* p) {
    uint32_t a;
    asm("{ .reg .u64 t; cvta.to.shared.u64 t, %1; cvt.u32.u64 %0, t; }" : "=r"(a) : "l"(p));
    return a;
}

__device__ __forceinline__ uint32_t h2(float lo, float hi) {
    __half2 h = __floats2half2_rn(lo, hi);
    return *(uint32_t*)&h;
}

__device__ __forceinline__ void mma16(float c[4],
                                      uint32_t a0, uint32_t a1, uint32_t a2, uint32_t a3,
                                      uint32_t b0, uint32_t b1) {
    asm volatile(
        "mma.sync.aligned.m16n8k16.row.col.f32.f16.f16.f32 "
        "{%0,%1,%2,%3}, {%4,%5,%6,%7}, {%8,%9}, {%0,%1,%2,%3};"
        : "+f"(c[0]), "+f"(c[1]), "+f"(c[2]), "+f"(c[3])
        : "r"(a0), "r"(a1), "r"(a2), "r"(a3), "r"(b0), "r"(b1));
}

#define CP16(dst, src) \
    asm volatile("cp.async.cg.shared.global [%0], [%1], 16;" :: "r"(dst), "l"(src) : "memory")
#define CP_COMMIT() asm volatile("cp.async.commit_group;" ::: "memory")
#define CP_WAIT2()  asm volatile("cp.async.wait_group 2;" ::: "memory")
#define CP_WAIT0()  asm volatile("cp.async.wait_group 0;" ::: "memory")

#define AWORDS 2048
// Both GEMMs: 4 A-stage buffers (words 0..8192) + resident B (words 8192..24576)
#define GEMM_SMEM_BYTES (24576 * 4)              // 98304
#define CVTX_SMEM (256 * 132 * 2)                // 67584

// ---------------------------------------------------------------------------
// GEMM 1 (B-resident): one CTA owns ALL 768 out-channels for its 128 tokens.
// B (64KB) staged once (commit group 0); A streamed through a flat 48-stage,
// 4-buffer, 3-in-flight cp.async chain. At compute stage gs the oldest
// committed groups (B, A0..Ags) must be complete -> wait_group 2.
// ---------------------------------------------------------------------------
__global__ __launch_bounds__(128) void qkv_mma(const float* __restrict__ bias)
{
    extern __shared__ uint32_t dsm[];
    const uint32_t smbase = smem_u32(dsm);

    const int tid  = threadIdx.x;
    const int lane = tid & 31;
    const int wid  = tid >> 5;
    const int g    = lane >> 2;
    const int t4   = lane & 3;
    const int wm   = wid >> 1;
    const int wn   = wid & 1;

    const int gy = blockIdx.x;
    const int b  = gy >> 9;
    const int tl = gy & 511;
    const int w0 = tl << 1;

    const uint32_t* gB = h_x + (size_t)b * 8388608 + (size_t)tl * 16384;

    // Stage resident B (64KB) as cp.async group 0.
#pragma unroll
    for (int i = 0; i < 32; ++i) {
        int c = tid + (i << 7);
        CP16(smbase + (uint32_t)(8192 + c * 4) * 4u, gB + (size_t)c * 4);
    }
    CP_COMMIT();

    // A stage issue: global stage gs in [0,48); buffer gs & 3.
#define QISSUE(GS)                                                             \
    do {                                                                       \
        const int _gs = (GS);                                                  \
        const uint32_t _aB = smbase + (uint32_t)((_gs & 3) * AWORDS) * 4u;     \
        const uint32_t* _gA = h_wq + (size_t)(_gs >> 3) * 16384;               \
        _Pragma("unroll")                                                      \
        for (int _i = 0; _i < 4; ++_i) {                                       \
            int _c = tid + (_i << 7);                                          \
            CP16(_aB + (uint32_t)_c * 16u,                                     \
                 _gA + ((size_t)(_c >> 6) * 2048 + (_gs & 7) * 256             \
                        + (_c & 63) * 4));                                     \
        }                                                                      \
        CP_COMMIT();                                                           \
    } while (0)

    QISSUE(0);
    QISSUE(1);
    QISSUE(2);

    const int e  = g & 1;
    const int pj = g >> 1;

#pragma unroll 1
    for (int m = 0; m < 6; ++m) {
        float acc[4][8][4];
#pragma unroll
        for (int mt = 0; mt < 4; ++mt)
#pragma unroll
            for (int nt = 0; nt < 8; ++nt)
#pragma unroll
                for (int r = 0; r < 4; ++r) acc[mt][nt][r] = 0.f;

#pragma unroll 1
        for (int s = 0; s < 8; ++s) {
            const int gs = m * 8 + s;
            if (gs < 45) { CP_WAIT2(); } else { CP_WAIT0(); }
            __syncthreads();
            if (gs + 3 < 48) QISSUE(gs + 3);

            const uint32_t* _A = dsm + (gs & 3) * AWORDS;
            const uint32_t* _B = dsm + 8192;
            uint4 bf[8];
#pragma unroll
            for (int nt = 0; nt < 8; ++nt)
                bf[nt] = *(const uint4*)(_B + (wn * 8 + nt) * 1024 + s * 128
                                              + (lane << 2));
#pragma unroll
            for (int ks = 0; ks < 2; ++ks) {
                uint4 af[4];
#pragma unroll
                for (int mt = 0; mt < 4; ++mt)
                    af[mt] = *(const uint4*)(_A + (((wm * 4 + mt) * 2 + ks) << 7)
                                                  + (lane << 2));
#pragma unroll
                for (int mt = 0; mt < 4; ++mt)
#pragma unroll
                    for (int nt = 0; nt < 8; ++nt)
                        mma16(acc[mt][nt], af[mt].x, af[mt].y, af[mt].z, af[mt].w,
                              ks ? bf[nt].z : bf[nt].x, ks ? bf[nt].w : bf[nt].y);
            }
        }

        // Epilogue for M-tile m (identical math to Round 8)
        const int g64  = 2 * m + wm;
        const int head = g64 / 3;
        const int typ  = g64 % 3;
        const size_t ubase = (size_t)((b * 4 + head) * 1024 + w0 + wn) * 2048;

        if (typ == 0) {
            uint32_t* gout = h_qkv + ubase;
#pragma unroll
            for (int mt = 0; mt < 4; ++mt)
#pragma unroll
                for (int half = 0; half < 2; ++half) {
                    const float bv = bias[g64 * 64 + mt * 16 + 8 * half + g];
#pragma unroll
                    for (int nt = 0; nt < 8; ++nt) {
                        float v0 = 0.125f * (acc[mt][nt][2 * half + 0] + bv);
                        float v1 = 0.125f * (acc[mt][nt][2 * half + 1] + bv);
                        float p0 = __shfl_xor_sync(0xffffffffu, v0, 4);
                        float p1 = __shfl_xor_sync(0xffffffffu, v1, 4);
                        float lo = e ? p1 : v0;
                        float hi = e ? v1 : p0;
                        int word = (nt >> 1) * 512 + mt * 128
                                   + ((2 * t4 + e) * 4 + pj) * 4 + half * 2 + (nt & 1);
                        gout[word] = h2(lo, hi);
                    }
                }
        } else if (typ == 1) {
            uint32_t* gout = h_qkv + KOFF + ubase;
#pragma unroll
            for (int mt = 0; mt < 4; ++mt)
#pragma unroll
                for (int half = 0; half < 2; ++half) {
                    const float bv = bias[g64 * 64 + mt * 16 + 8 * half + g];
#pragma unroll
                    for (int nt = 0; nt < 8; ++nt) {
                        float v0 = acc[mt][nt][2 * half + 0] + bv;
                        float v1 = acc[mt][nt][2 * half + 1] + bv;
                        float p0 = __shfl_xor_sync(0xffffffffu, v0, 4);
                        float p1 = __shfl_xor_sync(0xffffffffu, v1, 4);
                        float lo = e ? p1 : v0;
                        float hi = e ? v1 : p0;
                        int word = (nt * 2 + (mt >> 1)) * 128
                                   + ((2 * t4 + e) * 4 + pj) * 4 + (mt & 1) * 2 + half;
                        gout[word] = h2(lo, hi);
                    }
                }
        } else {
            uint32_t* gout = h_qkv + VOFF + ubase;
#pragma unroll
            for (int mt = 0; mt < 4; ++mt)
#pragma unroll
                for (int half = 0; half < 2; ++half) {
                    const float bv = bias[g64 * 64 + mt * 16 + 8 * half + g];
#pragma unroll
                    for (int nt = 0; nt < 8; ++nt) {
                        float v0 = acc[mt][nt][2 * half + 0] + bv;
                        float v1 = acc[mt][nt][2 * half + 1] + bv;
                        int word = ((mt * 2 + half) * 2 + (nt >> 2)) * 128
                                   + (g * 4 + t4) * 4 + ((nt >> 1) & 1) * 2 + (nt & 1);
                        gout[word] = h2(v0, v1);
                    }
                }
        }
    }
#undef QISSUE
}

// ---------------------------------------------------------------------------
// GEMM 2 (B-resident): one CTA owns BOTH 128-channel M-tiles for its 128
// tokens. B staged once; A streamed through a flat 16-stage chain (wait 2).
// ---------------------------------------------------------------------------
__global__ __launch_bounds__(128) void proj_mma(const float* __restrict__ bias,
                                                float* __restrict__ out)
{
    extern __shared__ uint32_t dsm[];
    const uint32_t smbase = smem_u32(dsm);

    const int tid  = threadIdx.x;
    const int lane = tid & 31;
    const int wid  = tid >> 5;
    const int g    = lane >> 2;
    const int t4   = lane & 3;
    const int wm   = wid >> 1;
    const int wn   = wid & 1;

    const int gy = blockIdx.x;
    const int b  = gy >> 9;
    const int tl = gy & 511;
    const int w0 = tl << 1;

    const uint32_t* gB = h_attn + (size_t)b * 8388608 + (size_t)tl * 16384;

    // Stage resident B (64KB) as cp.async group 0.
#pragma unroll
    for (int i = 0; i < 32; ++i) {
        int c = tid + (i << 7);
        CP16(smbase + (uint32_t)(8192 + c * 4) * 4u, gB + (size_t)c * 4);
    }
    CP_COMMIT();

#define PISSUE(GS)                                                             \
    do {                                                                       \
        const int _gs = (GS);                                                  \
        const uint32_t _aB = smbase + (uint32_t)((_gs & 3) * AWORDS) * 4u;     \
        const uint32_t* _gA = h_wp + (size_t)(_gs >> 3) * 16384;               \
        _Pragma("unroll")                                                      \
        for (int _i = 0; _i < 4; ++_i) {                                       \
            int _c = tid + (_i << 7);                                          \
            CP16(_aB + (uint32_t)_c * 16u,                                     \
                 _gA + ((size_t)(_c >> 6) * 2048 + (_gs & 7) * 256             \
                        + (_c & 63) * 4));                                     \
        }                                                                      \
        CP_COMMIT();                                                           \
    } while (0)

    PISSUE(0);
    PISSUE(1);
    PISSUE(2);

#pragma unroll 1
    for (int m = 0; m < 2; ++m) {
        float acc[4][8][4];
#pragma unroll
        for (int mt = 0; mt < 4; ++mt)
#pragma unroll
            for (int nt = 0; nt < 8; ++nt)
#pragma unroll
                for (int r = 0; r < 4; ++r) acc[mt][nt][r] = 0.f;

#pragma unroll 1
        for (int s = 0; s < 8; ++s) {
            const int gs = m * 8 + s;
            if (gs < 13) { CP_WAIT2(); } else { CP_WAIT0(); }
            __syncthreads();
            if (gs + 3 < 16) PISSUE(gs + 3);

            const uint32_t* _A = dsm + (gs & 3) * AWORDS;
            const uint32_t* _B = dsm + 8192;
            uint4 bf[8];
#pragma unroll
            for (int nt = 0; nt < 8; ++nt)
                bf[nt] = *(const uint4*)(_B + (wn * 8 + nt) * 1024 + s * 128
                                              + (lane << 2));
#pragma unroll
            for (int ks = 0; ks < 2; ++ks) {
                uint4 af[4];
#pragma unroll
                for (int mt = 0; mt < 4; ++mt)
                    af[mt] = *(const uint4*)(_A + (((wm * 4 + mt) * 2 + ks) << 7)
                                                  + (lane << 2));
#pragma unroll
                for (int mt = 0; mt < 4; ++mt)
#pragma unroll
                    for (int nt = 0; nt < 8; ++nt)
                        mma16(acc[mt][nt], af[mt].x, af[mt].y, af[mt].z, af[mt].w,
                              ks ? bf[nt].z : bf[nt].x, ks ? bf[nt].w : bf[nt].y);
            }
        }

        const int m0 = m << 7;
#pragma unroll
        for (int mt = 0; mt < 4; ++mt) {
#pragma unroll
            for (int half = 0; half < 2; ++half) {
                const int o = m0 + wm * 64 + mt * 16 + g + half * 8;
                const float bv = bias[o];
                float* obase = out + ((size_t)b * 256 + o) * HW;
#pragma unroll
                for (int nt = 0; nt < 8; ++nt) {
                    const int col = wn * 64 + nt * 8 + 2 * t4;
                    const int win = w0 + (col >> 6);
                    const int t64 = col & 63;
                    const int y   = ((win >> 5) << 3) + (t64 >> 3);
                    const int xx  = ((win & 31) << 3) + (t64 & 7);
                    float2 ov = make_float2(acc[mt][nt][2 * half] + bv,
                                            acc[mt][nt][2 * half + 1] + bv);
                    *(float2*)(obase + y * IMW + xx) = ov;
                }
            }
        }
    }
#undef PISSUE
}

// ---------------------------------------------------------------------------
// Prepass: fp16-round weights into A-fragment-packed layout.
// ---------------------------------------------------------------------------
__global__ __launch_bounds__(256) void cvt_weights(const float* __restrict__ qw,
                                                   const float* __restrict__ pw)
{
    int i = blockIdx.x * 256 + threadIdx.x;
    if (i < 196608) {
        int o = i >> 8, c = i & 255;
        int word = (o >> 4) * 2048 + (c >> 4) * 128
                   + ((o & 7) * 4 + (((c & 15) & 7) >> 1)) * 4
                   + ((c >> 3) & 1) * 2 + ((o >> 3) & 1);
        ((__half*)h_wq)[word * 2 + (c & 1)] = __float2half_rn(qw[i]);
    }
    if (i < 65536) {
        int o = i >> 8, c = i & 255;
        int word = (o >> 4) * 2048 + (c >> 4) * 128
                   + ((o & 7) * 4 + (((c & 15) & 7) >> 1)) * 4
                   + ((c >> 3) & 1) * 2 + ((o >> 3) & 1);
        ((__half*)h_wp)[word * 2 + (c & 1)] = __float2half_rn(pw[i]);
    }
}

// ---------------------------------------------------------------------------
// Prepass: fp16 + window-major + B-fragment-pack x via smem transpose.
// ---------------------------------------------------------------------------
__global__ __launch_bounds__(256) void cvt_x(const float* __restrict__ x)
{
    extern __shared__ __half sh[];   // [256][132]
    const int bt = blockIdx.x;
    const int b  = bt >> 9, tl = bt & 511;
    const int tid = threadIdx.x;
    const int w0 = tl << 1;

#pragma unroll 4
    for (int it = 0; it < 32; ++it) {
        int idx = it * 256 + tid;
        int c = idx >> 5, tq = idx & 31;
        int tok4 = tq << 2;
        int win = w0 + (tok4 >> 6), t64 = tok4 & 63;
        int y = ((win >> 5) << 3) + (t64 >> 3), xx = ((win & 31) << 3) + (t64 & 7);
        float4 v = *(const float4*)(x + ((size_t)(b * 256 + c)) * HW + y * IMW + xx);
        __half2* dst = (__half2*)(sh + c * 132 + tok4);
        dst[0] = __floats2half2_rn(v.x, v.y);
        dst[1] = __floats2half2_rn(v.z, v.w);
    }
    __syncthreads();

    uint32_t* outp = h_x + (size_t)b * 8388608 + (size_t)tl * 16384;
#pragma unroll 4
    for (int it = 0; it < 64; ++it) {
        int widx = it * 256 + tid;
        int t8L = widx >> 10, rest = widx & 1023;
        int s = rest >> 7, lw = rest & 127;
        int lc = lw >> 2, sub = lw & 3;
        int ks = sub >> 1, r = sub & 1;
        int gg = lc >> 2, tt4 = lc & 3;
        int tok = t8L * 8 + gg;
        int c0 = s * 32 + ks * 16 + r * 8 + 2 * tt4;
        outp[widx] = h2(__half2float(sh[c0 * 132 + tok]),
                        __half2float(sh[(c0 + 1) * 132 + tok]));
    }
}

// ---------------------------------------------------------------------------
// fp16 tensor-core window attention (Round-8 exact).
// ---------------------------------------------------------------------------
__global__ __launch_bounds__(128) void attn_mma()
{
    __shared__ uint32_t sm[4096];    // K[2048] | V[2048]
    const uint32_t smbase = smem_u32(sm);

    const int tid  = threadIdx.x;
    const int lane = tid & 31;
    const int wrp  = tid >> 5;
    const int g    = lane >> 2;
    const int t4   = lane & 3;

    const int win = blockIdx.x;
    const int hd  = blockIdx.y;
    const int b   = blockIdx.z;

    const size_t unit = (size_t)((b * 4 + hd) * 1024 + win) * 2048;
    const uint32_t* gq = h_qkv + unit;
    const uint32_t* gk = h_qkv + KOFF + unit;
    const uint32_t* gv = h_qkv + VOFF + unit;

#pragma unroll
    for (int i = 0; i < 4; ++i) {
        int c = tid + i * 128;
        CP16(smbase + (uint32_t)c * 16u, gk + (size_t)c * 4);
        CP16(smbase + 8192u + (uint32_t)c * 16u, gv + (size_t)c * 4);
    }
    CP_COMMIT();

    uint4 qf[4];
#pragma unroll
    for (int kc = 0; kc < 4; ++kc)
        qf[kc] = *(const uint4*)(gq + wrp * 512 + kc * 128 + lane * 4);

    CP_WAIT0();
    __syncthreads();

    const uint32_t* ksm = sm;
    const uint32_t* vsm = sm + 2048;

    float acc[8][4];
#pragma unroll
    for (int nt = 0; nt < 8; ++nt)
#pragma unroll
        for (int r = 0; r < 4; ++r) acc[nt][r] = 0.f;

#pragma unroll
    for (int c32 = 0; c32 < 2; ++c32)
#pragma unroll
        for (int nt = 0; nt < 8; ++nt) {
            uint4 kf = *(const uint4*)(ksm + (nt * 2 + c32) * 128 + lane * 4);
            mma16(acc[nt], qf[2 * c32].x, qf[2 * c32].y, qf[2 * c32].z, qf[2 * c32].w,
                  kf.x, kf.y);
            mma16(acc[nt], qf[2 * c32 + 1].x, qf[2 * c32 + 1].y, qf[2 * c32 + 1].z,
                  qf[2 * c32 + 1].w, kf.z, kf.w);
        }

    float mx0 = -1e30f, mx1 = -1e30f;
#pragma unroll
    for (int nt = 0; nt < 8; ++nt) {
        mx0 = fmaxf(mx0, fmaxf(acc[nt][0], acc[nt][1]));
        mx1 = fmaxf(mx1, fmaxf(acc[nt][2], acc[nt][3]));
    }
    mx0 = fmaxf(mx0, __shfl_xor_sync(0xffffffffu, mx0, 1));
    mx0 = fmaxf(mx0, __shfl_xor_sync(0xffffffffu, mx0, 2));
    mx1 = fmaxf(mx1, __shfl_xor_sync(0xffffffffu, mx1, 1));
    mx1 = fmaxf(mx1, __shfl_xor_sync(0xffffffffu, mx1, 2));

    float sm0 = 0.f, sm1 = 0.f;
#pragma unroll
    for (int nt = 0; nt < 8; ++nt) {
        acc[nt][0] = __expf(acc[nt][0] - mx0);
        acc[nt][1] = __expf(acc[nt][1] - mx0);
        acc[nt][2] = __expf(acc[nt][2] - mx1);
        acc[nt][3] = __expf(acc[nt][3] - mx1);
        sm0 += acc[nt][0] + acc[nt][1];
        sm1 += acc[nt][2] + acc[nt][3];
    }
    sm0 += __shfl_xor_sync(0xffffffffu, sm0, 1);
    sm0 += __shfl_xor_sync(0xffffffffu, sm0, 2);
    sm1 += __shfl_xor_sync(0xffffffffu, sm1, 1);
    sm1 += __shfl_xor_sync(0xffffffffu, sm1, 2);
    const float inv0 = 1.0f / sm0;
    const float inv1 = 1.0f / sm1;

    uint32_t pa[4][4];
#pragma unroll
    for (int u = 0; u < 4; ++u) {
        pa[u][0] = h2(acc[2 * u][0],     acc[2 * u][1]);
        pa[u][1] = h2(acc[2 * u][2],     acc[2 * u][3]);
        pa[u][2] = h2(acc[2 * u + 1][0], acc[2 * u + 1][1]);
        pa[u][3] = h2(acc[2 * u + 1][2], acc[2 * u + 1][3]);
    }

    float oac[8][4];
#pragma unroll
    for (int nt = 0; nt < 8; ++nt)
#pragma unroll
        for (int r = 0; r < 4; ++r) oac[nt][r] = 0.f;

#pragma unroll
    for (int uc32 = 0; uc32 < 2; ++uc32)
#pragma unroll
        for (int nt = 0; nt < 8; ++nt) {
            uint4 vf = *(const uint4*)(vsm + (nt * 2 + uc32) * 128 + lane * 4);
            mma16(oac[nt], pa[2 * uc32][0], pa[2 * uc32][1], pa[2 * uc32][2],
                  pa[2 * uc32][3], vf.x, vf.y);
            mma16(oac[nt], pa[2 * uc32 + 1][0], pa[2 * uc32 + 1][1],
                  pa[2 * uc32 + 1][2], pa[2 * uc32 + 1][3], vf.z, vf.w);
        }

    uint32_t* ga = h_attn + (size_t)b * 8388608;
    const int t8b = win * 8 + wrp * 2;
#pragma unroll
    for (int nt = 0; nt < 8; ++nt) {
        const int s  = hd * 2 + (nt >> 2);
        const int ks = (nt >> 1) & 1;
        const int r  = nt & 1;
#pragma unroll
        for (int rh = 0; rh < 2; ++rh) {
            const float inv = rh ? inv1 : inv0;
            int word = (t8b + rh) * 1024 + s * 128 + (g * 4 + t4) * 4 + ks * 2 + r;
            ga[word] = h2(oac[nt][2 * rh] * inv, oac[nt][2 * rh + 1] * inv);
        }
    }
}

// ---------------------------------------------------------------------------
extern "C" void kernel_launch(void* const* d_in, const int* in_sizes, int n_in,
                              void* d_out, int out_size)
{
    (void)in_sizes; (void)n_in; (void)out_size;
    const float* x      = (const float*)d_in[0];
    const float* qkv_w  = (const float*)d_in[1];
    const float* qkv_b  = (const float*)d_in[2];
    const float* proj_w = (const float*)d_in[3];
    const float* proj_b = (const float*)d_in[4];
    float* out = (float*)d_out;

    static int attr_done = 0;
    if (!attr_done) {
        cudaFuncSetAttribute(qkv_mma,  cudaFuncAttributeMaxDynamicSharedMemorySize, GEMM_SMEM_BYTES);
        cudaFuncSetAttribute(proj_mma, cudaFuncAttributeMaxDynamicSharedMemorySize, GEMM_SMEM_BYTES);
        cudaFuncSetAttribute(cvt_x,    cudaFuncAttributeMaxDynamicSharedMemorySize, CVTX_SMEM);
        attr_done = 1;
    }

    cvt_weights<<<768, 256>>>(qkv_w, proj_w);
    cvt_x<<<4096, 256, CVTX_SMEM>>>(x);
    qkv_mma<<<4096, 128, GEMM_SMEM_BYTES>>>(qkv_b);
    attn_mma<<<dim3(1024, 4, 8), 128>>>();
    proj_mma<<<4096, 128, GEMM_SMEM_BYTES>>>(proj_b, out);
}

// round 15
// speedup vs baseline: 1.2747x; 1.0654x over previous
#include <cuda_runtime.h>
#include <cuda_fp16.h>
#include <math.h>
#include <stdint.h>

// Problem constants: B=8, C=256, H=W=256, WS=8, HEADS=4, dh=64
#define HW  65536
#define IMW 256

// fp16 fragment-packed scratch (all m16n8k16 layouts), stored as u32 (half2):
//  h_qkv: Q | K | V regions, 2048 words per (b,hd,win) unit.
//  h_attn (GEMM B): [b][t8 8192][s 8][lane*4 + ks*2 + r] (pairs over chan)
//  h_wq / h_wp (GEMM A): [mt][k16 16][lane*4 + hik*2 + him]
__device__ uint32_t h_qkv[201326592];
__device__ uint32_t h_attn[67108864];
__device__ uint32_t h_wq[98304];
__device__ uint32_t h_wp[32768];

#define KOFF 67108864
#define VOFF 134217728

__device__ __forceinline__ uint32_t smem_u32(const void* p) {
    uint32_t a;
    asm("{ .reg .u64 t; cvta.to.shared.u64 t, %1; cvt.u32.u64 %0, t; }" : "=r"(a) : "l"(p));
    return a;
}

__device__ __forceinline__ uint32_t h2(float lo, float hi) {
    __half2 h = __floats2half2_rn(lo, hi);
    return *(uint32_t*)&h;
}

__device__ __forceinline__ void mma16(float c[4],
                                      uint32_t a0, uint32_t a1, uint32_t a2, uint32_t a3,
                                      uint32_t b0, uint32_t b1) {
    asm volatile(
        "mma.sync.aligned.m16n8k16.row.col.f32.f16.f16.f32 "
        "{%0,%1,%2,%3}, {%4,%5,%6,%7}, {%8,%9}, {%0,%1,%2,%3};"
        : "+f"(c[0]), "+f"(c[1]), "+f"(c[2]), "+f"(c[3])
        : "r"(a0), "r"(a1), "r"(a2), "r"(a3), "r"(b0), "r"(b1));
}

#define CP16(dst, src) \
    asm volatile("cp.async.cg.shared.global [%0], [%1], 16;" :: "r"(dst), "l"(src) : "memory")
#define CP_COMMIT() asm volatile("cp.async.commit_group;" ::: "memory")
#define CP_WAIT2()  asm volatile("cp.async.wait_group 2;" ::: "memory")
#define CP_WAIT0()  asm volatile("cp.async.wait_group 0;" ::: "memory")

#define AWORDS 2048
// Both GEMMs: 4 A-stage buffers (words 0..8192) + resident B (words 8192..24576)
#define GEMM_SMEM_BYTES (24576 * 4)              // 98304

// ---------------------------------------------------------------------------
// GEMM 1 (B-resident, cvt-fused): one CTA owns ALL 768 out-channels for its
// 128 tokens. The resident fp16 B tile is built IN-KERNEL from raw fp32 x
// (4 chunks of 64 channels; coalesced LDG -> [c][tok] half transpose in the
// A-buffer scratch -> fragment-packed repack; value chain identical to the
// old cvt_x kernel). A streams through a 48-stage, 4-buffer, 3-in-flight
// cp.async chain (at stage gs, A0..A(gs+2) committed -> wait_group 2).
// ---------------------------------------------------------------------------
__global__ __launch_bounds__(128) void qkv_mma(const float* __restrict__ x,
                                               const float* __restrict__ bias)
{
    extern __shared__ uint32_t dsm[];
    const uint32_t smbase = smem_u32(dsm);

    const int tid  = threadIdx.x;
    const int lane = tid & 31;
    const int wid  = tid >> 5;
    const int g    = lane >> 2;
    const int t4   = lane & 3;
    const int wm   = wid >> 1;
    const int wn   = wid & 1;

    const int gy = blockIdx.x;
    const int b  = gy >> 9;
    const int tl = gy & 511;
    const int w0 = tl << 1;

    // ---- Build resident fp16 B tile from raw x (replaces cvt_x + h_x) ----
    const float* xb = x + (size_t)b * 256 * HW;
    __half* sc = (__half*)dsm;    // scratch [64][132] halfs in A-buffer region

#pragma unroll 1
    for (int chunk = 0; chunk < 4; ++chunk) {
        const int cbase = chunk << 6;
        // Phase 1: coalesced fp32 loads -> [c][tok] half transpose (scratch).
#pragma unroll
        for (int it = 0; it < 16; ++it) {
            int idx = it * 128 + tid;
            int c = idx >> 5, tq = idx & 31;
            int tok4 = tq << 2;
            int win = w0 + (tok4 >> 6), t64 = tok4 & 63;
            int y  = ((win >> 5) << 3) + (t64 >> 3);
            int xx = ((win & 31) << 3) + (t64 & 7);
            float4 v = *(const float4*)(xb + (size_t)(cbase + c) * HW + y * IMW + xx);
            __half2* dst = (__half2*)(sc + c * 132 + tok4);
            dst[0] = __floats2half2_rn(v.x, v.y);
            dst[1] = __floats2half2_rn(v.z, v.w);
        }
        __syncthreads();
        // Phase 2: repack into fragment-packed resident B (words 8192..).
#pragma unroll
        for (int it = 0; it < 32; ++it) {
            int w = it * 128 + tid;
            int t8L = w >> 8;
            int rest = w & 255;
            int sL = rest >> 7, lw = rest & 127;
            int lc = lw >> 2, sub = lw & 3;
            int ks = sub >> 1, r = sub & 1;
            int gg = lc >> 2, tt4 = lc & 3;
            int tok = t8L * 8 + gg;
            int cl  = sL * 32 + ks * 16 + r * 8 + 2 * tt4;
            dsm[8192 + t8L * 1024 + (chunk * 2 + sL) * 128 + lw] =
                h2(__half2float(sc[cl * 132 + tok]),
                   __half2float(sc[(cl + 1) * 132 + tok]));
        }
        __syncthreads();
    }

    // A stage issue: global stage gs in [0,48); buffer gs & 3.
#define QISSUE(GS)                                                             \
    do {                                                                       \
        const int _gs = (GS);                                                  \
        const uint32_t _aB = smbase + (uint32_t)((_gs & 3) * AWORDS) * 4u;     \
        const uint32_t* _gA = h_wq + (size_t)(_gs >> 3) * 16384;               \
        _Pragma("unroll")                                                      \
        for (int _i = 0; _i < 4; ++_i) {                                       \
            int _c = tid + (_i << 7);                                          \
            CP16(_aB + (uint32_t)_c * 16u,                                     \
                 _gA + ((size_t)(_c >> 6) * 2048 + (_gs & 7) * 256             \
                        + (_c & 63) * 4));                                     \
        }                                                                      \
        CP_COMMIT();                                                           \
    } while (0)

    QISSUE(0);
    QISSUE(1);
    QISSUE(2);

    const int e  = g & 1;
    const int pj = g >> 1;

#pragma unroll 1
    for (int m = 0; m < 6; ++m) {
        float acc[4][8][4];
#pragma unroll
        for (int mt = 0; mt < 4; ++mt)
#pragma unroll
            for (int nt = 0; nt < 8; ++nt)
#pragma unroll
                for (int r = 0; r < 4; ++r) acc[mt][nt][r] = 0.f;

#pragma unroll 1
        for (int s = 0; s < 8; ++s) {
            const int gs = m * 8 + s;
            if (gs < 45) { CP_WAIT2(); } else { CP_WAIT0(); }
            __syncthreads();
            if (gs + 3 < 48) QISSUE(gs + 3);

            const uint32_t* _A = dsm + (gs & 3) * AWORDS;
            const uint32_t* _B = dsm + 8192;
            uint4 bf[8];
#pragma unroll
            for (int nt = 0; nt < 8; ++nt)
                bf[nt] = *(const uint4*)(_B + (wn * 8 + nt) * 1024 + s * 128
                                              + (lane << 2));
#pragma unroll
            for (int ks = 0; ks < 2; ++ks) {
                uint4 af[4];
#pragma unroll
                for (int mt = 0; mt < 4; ++mt)
                    af[mt] = *(const uint4*)(_A + (((wm * 4 + mt) * 2 + ks) << 7)
                                                  + (lane << 2));
#pragma unroll
                for (int mt = 0; mt < 4; ++mt)
#pragma unroll
                    for (int nt = 0; nt < 8; ++nt)
                        mma16(acc[mt][nt], af[mt].x, af[mt].y, af[mt].z, af[mt].w,
                              ks ? bf[nt].z : bf[nt].x, ks ? bf[nt].w : bf[nt].y);
            }
        }

        // Epilogue for M-tile m (identical math to Round 8)
        const int g64  = 2 * m + wm;
        const int head = g64 / 3;
        const int typ  = g64 % 3;
        const size_t ubase = (size_t)((b * 4 + head) * 1024 + w0 + wn) * 2048;

        if (typ == 0) {
            uint32_t* gout = h_qkv + ubase;
#pragma unroll
            for (int mt = 0; mt < 4; ++mt)
#pragma unroll
                for (int half = 0; half < 2; ++half) {
                    const float bv = bias[g64 * 64 + mt * 16 + 8 * half + g];
#pragma unroll
                    for (int nt = 0; nt < 8; ++nt) {
                        float v0 = 0.125f * (acc[mt][nt][2 * half + 0] + bv);
                        float v1 = 0.125f * (acc[mt][nt][2 * half + 1] + bv);
                        float p0 = __shfl_xor_sync(0xffffffffu, v0, 4);
                        float p1 = __shfl_xor_sync(0xffffffffu, v1, 4);
                        float lo = e ? p1 : v0;
                        float hi = e ? v1 : p0;
                        int word = (nt >> 1) * 512 + mt * 128
                                   + ((2 * t4 + e) * 4 + pj) * 4 + half * 2 + (nt & 1);
                        gout[word] = h2(lo, hi);
                    }
                }
        } else if (typ == 1) {
            uint32_t* gout = h_qkv + KOFF + ubase;
#pragma unroll
            for (int mt = 0; mt < 4; ++mt)
#pragma unroll
                for (int half = 0; half < 2; ++half) {
                    const float bv = bias[g64 * 64 + mt * 16 + 8 * half + g];
#pragma unroll
                    for (int nt = 0; nt < 8; ++nt) {
                        float v0 = acc[mt][nt][2 * half + 0] + bv;
                        float v1 = acc[mt][nt][2 * half + 1] + bv;
                        float p0 = __shfl_xor_sync(0xffffffffu, v0, 4);
                        float p1 = __shfl_xor_sync(0xffffffffu, v1, 4);
                        float lo = e ? p1 : v0;
                        float hi = e ? v1 : p0;
                        int word = (nt * 2 + (mt >> 1)) * 128
                                   + ((2 * t4 + e) * 4 + pj) * 4 + (mt & 1) * 2 + half;
                        gout[word] = h2(lo, hi);
                    }
                }
        } else {
            uint32_t* gout = h_qkv + VOFF + ubase;
#pragma unroll
            for (int mt = 0; mt < 4; ++mt)
#pragma unroll
                for (int half = 0; half < 2; ++half) {
                    const float bv = bias[g64 * 64 + mt * 16 + 8 * half + g];
#pragma unroll
                    for (int nt = 0; nt < 8; ++nt) {
                        float v0 = acc[mt][nt][2 * half + 0] + bv;
                        float v1 = acc[mt][nt][2 * half + 1] + bv;
                        int word = ((mt * 2 + half) * 2 + (nt >> 2)) * 128
                                   + (g * 4 + t4) * 4 + ((nt >> 1) & 1) * 2 + (nt & 1);
                        gout[word] = h2(v0, v1);
                    }
                }
        }
    }
#undef QISSUE
}

// ---------------------------------------------------------------------------
// GEMM 2 (B-resident): one CTA owns BOTH 128-channel M-tiles for its 128
// tokens. B staged once (group 0); A streams (wait_group 2). Round-14 exact.
// ---------------------------------------------------------------------------
__global__ __launch_bounds__(128) void proj_mma(const float* __restrict__ bias,
                                                float* __restrict__ out)
{
    extern __shared__ uint32_t dsm[];
    const uint32_t smbase = smem_u32(dsm);

    const int tid  = threadIdx.x;
    const int lane = tid & 31;
    const int wid  = tid >> 5;
    const int g    = lane >> 2;
    const int t4   = lane & 3;
    const int wm   = wid >> 1;
    const int wn   = wid & 1;

    const int gy = blockIdx.x;
    const int b  = gy >> 9;
    const int tl = gy & 511;
    const int w0 = tl << 1;

    const uint32_t* gB = h_attn + (size_t)b * 8388608 + (size_t)tl * 16384;

    // Stage resident B (64KB) as cp.async group 0.
#pragma unroll
    for (int i = 0; i < 32; ++i) {
        int c = tid + (i << 7);
        CP16(smbase + (uint32_t)(8192 + c * 4) * 4u, gB + (size_t)c * 4);
    }
    CP_COMMIT();

#define PISSUE(GS)                                                             \
    do {                                                                       \
        const int _gs = (GS);                                                  \
        const uint32_t _aB = smbase + (uint32_t)((_gs & 3) * AWORDS) * 4u;     \
        const uint32_t* _gA = h_wp + (size_t)(_gs >> 3) * 16384;               \
        _Pragma("unroll")                                                      \
        for (int _i = 0; _i < 4; ++_i) {                                       \
            int _c = tid + (_i << 7);                                          \
            CP16(_aB + (uint32_t)_c * 16u,                                     \
                 _gA + ((size_t)(_c >> 6) * 2048 + (_gs & 7) * 256             \
                        + (_c & 63) * 4));                                     \
        }                                                                      \
        CP_COMMIT();                                                           \
    } while (0)

    PISSUE(0);
    PISSUE(1);
    PISSUE(2);

#pragma unroll 1
    for (int m = 0; m < 2; ++m) {
        float acc[4][8][4];
#pragma unroll
        for (int mt = 0; mt < 4; ++mt)
#pragma unroll
            for (int nt = 0; nt < 8; ++nt)
#pragma unroll
                for (int r = 0; r < 4; ++r) acc[mt][nt][r] = 0.f;

#pragma unroll 1
        for (int s = 0; s < 8; ++s) {
            const int gs = m * 8 + s;
            if (gs < 13) { CP_WAIT2(); } else { CP_WAIT0(); }
            __syncthreads();
            if (gs + 3 < 16) PISSUE(gs + 3);

            const uint32_t* _A = dsm + (gs & 3) * AWORDS;
            const uint32_t* _B = dsm + 8192;
            uint4 bf[8];
#pragma unroll
            for (int nt = 0; nt < 8; ++nt)
                bf[nt] = *(const uint4*)(_B + (wn * 8 + nt) * 1024 + s * 128
                                              + (lane << 2));
#pragma unroll
            for (int ks = 0; ks < 2; ++ks) {
                uint4 af[4];
#pragma unroll
                for (int mt = 0; mt < 4; ++mt)
                    af[mt] = *(const uint4*)(_A + (((wm * 4 + mt) * 2 + ks) << 7)
                                                  + (lane << 2));
#pragma unroll
                for (int mt = 0; mt < 4; ++mt)
#pragma unroll
                    for (int nt = 0; nt < 8; ++nt)
                        mma16(acc[mt][nt], af[mt].x, af[mt].y, af[mt].z, af[mt].w,
                              ks ? bf[nt].z : bf[nt].x, ks ? bf[nt].w : bf[nt].y);
            }
        }

        const int m0 = m << 7;
#pragma unroll
        for (int mt = 0; mt < 4; ++mt) {
#pragma unroll
            for (int half = 0; half < 2; ++half) {
                const int o = m0 + wm * 64 + mt * 16 + g + half * 8;
                const float bv = bias[o];
                float* obase = out + ((size_t)b * 256 + o) * HW;
#pragma unroll
                for (int nt = 0; nt < 8; ++nt) {
                    const int col = wn * 64 + nt * 8 + 2 * t4;
                    const int win = w0 + (col >> 6);
                    const int t64 = col & 63;
                    const int y   = ((win >> 5) << 3) + (t64 >> 3);
                    const int xx  = ((win & 31) << 3) + (t64 & 7);
                    float2 ov = make_float2(acc[mt][nt][2 * half] + bv,
                                            acc[mt][nt][2 * half + 1] + bv);
                    *(float2*)(obase + y * IMW + xx) = ov;
                }
            }
        }
    }
#undef PISSUE
}

// ---------------------------------------------------------------------------
// Prepass: fp16-round weights into A-fragment-packed layout.
// ---------------------------------------------------------------------------
__global__ __launch_bounds__(256) void cvt_weights(const float* __restrict__ qw,
                                                   const float* __restrict__ pw)
{
    int i = blockIdx.x * 256 + threadIdx.x;
    if (i < 196608) {
        int o = i >> 8, c = i & 255;
        int word = (o >> 4) * 2048 + (c >> 4) * 128
                   + ((o & 7) * 4 + (((c & 15) & 7) >> 1)) * 4
                   + ((c >> 3) & 1) * 2 + ((o >> 3) & 1);
        ((__half*)h_wq)[word * 2 + (c & 1)] = __float2half_rn(qw[i]);
    }
    if (i < 65536) {
        int o = i >> 8, c = i & 255;
        int word = (o >> 4) * 2048 + (c >> 4) * 128
                   + ((o & 7) * 4 + (((c & 15) & 7) >> 1)) * 4
                   + ((c >> 3) & 1) * 2 + ((o >> 3) & 1);
        ((__half*)h_wp)[word * 2 + (c & 1)] = __float2half_rn(pw[i]);
    }
}

// ---------------------------------------------------------------------------
// fp16 tensor-core window attention (Round-8 exact).
// ---------------------------------------------------------------------------
__global__ __launch_bounds__(128) void attn_mma()
{
    __shared__ uint32_t sm[4096];    // K[2048] | V[2048]
    const uint32_t smbase = smem_u32(sm);

    const int tid  = threadIdx.x;
    const int lane = tid & 31;
    const int wrp  = tid >> 5;
    const int g    = lane >> 2;
    const int t4   = lane & 3;

    const int win = blockIdx.x;
    const int hd  = blockIdx.y;
    const int b   = blockIdx.z;

    const size_t unit = (size_t)((b * 4 + hd) * 1024 + win) * 2048;
    const uint32_t* gq = h_qkv + unit;
    const uint32_t* gk = h_qkv + KOFF + unit;
    const uint32_t* gv = h_qkv + VOFF + unit;

#pragma unroll
    for (int i = 0; i < 4; ++i) {
        int c = tid + i * 128;
        CP16(smbase + (uint32_t)c * 16u, gk + (size_t)c * 4);
        CP16(smbase + 8192u + (uint32_t)c * 16u, gv + (size_t)c * 4);
    }
    CP_COMMIT();

    uint4 qf[4];
#pragma unroll
    for (int kc = 0; kc < 4; ++kc)
        qf[kc] = *(const uint4*)(gq + wrp * 512 + kc * 128 + lane * 4);

    CP_WAIT0();
    __syncthreads();

    const uint32_t* ksm = sm;
    const uint32_t* vsm = sm + 2048;

    float acc[8][4];
#pragma unroll
    for (int nt = 0; nt < 8; ++nt)
#pragma unroll
        for (int r = 0; r < 4; ++r) acc[nt][r] = 0.f;

#pragma unroll
    for (int c32 = 0; c32 < 2; ++c32)
#pragma unroll
        for (int nt = 0; nt < 8; ++nt) {
            uint4 kf = *(const uint4*)(ksm + (nt * 2 + c32) * 128 + lane * 4);
            mma16(acc[nt], qf[2 * c32].x, qf[2 * c32].y, qf[2 * c32].z, qf[2 * c32].w,
                  kf.x, kf.y);
            mma16(acc[nt], qf[2 * c32 + 1].x, qf[2 * c32 + 1].y, qf[2 * c32 + 1].z,
                  qf[2 * c32 + 1].w, kf.z, kf.w);
        }

    float mx0 = -1e30f, mx1 = -1e30f;
#pragma unroll
    for (int nt = 0; nt < 8; ++nt) {
        mx0 = fmaxf(mx0, fmaxf(acc[nt][0], acc[nt][1]));
        mx1 = fmaxf(mx1, fmaxf(acc[nt][2], acc[nt][3]));
    }
    mx0 = fmaxf(mx0, __shfl_xor_sync(0xffffffffu, mx0, 1));
    mx0 = fmaxf(mx0, __shfl_xor_sync(0xffffffffu, mx0, 2));
    mx1 = fmaxf(mx1, __shfl_xor_sync(0xffffffffu, mx1, 1));
    mx1 = fmaxf(mx1, __shfl_xor_sync(0xffffffffu, mx1, 2));

    float sm0 = 0.f, sm1 = 0.f;
#pragma unroll
    for (int nt = 0; nt < 8; ++nt) {
        acc[nt][0] = __expf(acc[nt][0] - mx0);
        acc[nt][1] = __expf(acc[nt][1] - mx0);
        acc[nt][2] = __expf(acc[nt][2] - mx1);
        acc[nt][3] = __expf(acc[nt][3] - mx1);
        sm0 += acc[nt][0] + acc[nt][1];
        sm1 += acc[nt][2] + acc[nt][3];
    }
    sm0 += __shfl_xor_sync(0xffffffffu, sm0, 1);
    sm0 += __shfl_xor_sync(0xffffffffu, sm0, 2);
    sm1 += __shfl_xor_sync(0xffffffffu, sm1, 1);
    sm1 += __shfl_xor_sync(0xffffffffu, sm1, 2);
    const float inv0 = 1.0f / sm0;
    const float inv1 = 1.0f / sm1;

    uint32_t pa[4][4];
#pragma unroll
    for (int u = 0; u < 4; ++u) {
        pa[u][0] = h2(acc[2 * u][0],     acc[2 * u][1]);
        pa[u][1] = h2(acc[2 * u][2],     acc[2 * u][3]);
        pa[u][2] = h2(acc[2 * u + 1][0], acc[2 * u + 1][1]);
        pa[u][3] = h2(acc[2 * u + 1][2], acc[2 * u + 1][3]);
    }

    float oac[8][4];
#pragma unroll
    for (int nt = 0; nt < 8; ++nt)
#pragma unroll
        for (int r = 0; r < 4; ++r) oac[nt][r] = 0.f;

#pragma unroll
    for (int uc32 = 0; uc32 < 2; ++uc32)
#pragma unroll
        for (int nt = 0; nt < 8; ++nt) {
            uint4 vf = *(const uint4*)(vsm + (nt * 2 + uc32) * 128 + lane * 4);
            mma16(oac[nt], pa[2 * uc32][0], pa[2 * uc32][1], pa[2 * uc32][2],
                  pa[2 * uc32][3], vf.x, vf.y);
            mma16(oac[nt], pa[2 * uc32 + 1][0], pa[2 * uc32 + 1][1],
                  pa[2 * uc32 + 1][2], pa[2 * uc32 + 1][3], vf.z, vf.w);
        }

    uint32_t* ga = h_attn + (size_t)b * 8388608;
    const int t8b = win * 8 + wrp * 2;
#pragma unroll
    for (int nt = 0; nt < 8; ++nt) {
        const int s  = hd * 2 + (nt >> 2);
        const int ks = (nt >> 1) & 1;
        const int r  = nt & 1;
#pragma unroll
        for (int rh = 0; rh < 2; ++rh) {
            const float inv = rh ? inv1 : inv0;
            int word = (t8b + rh) * 1024 + s * 128 + (g * 4 + t4) * 4 + ks * 2 + r;
            ga[word] = h2(oac[nt][2 * rh] * inv, oac[nt][2 * rh + 1] * inv);
        }
    }
}

// ---------------------------------------------------------------------------
extern "C" void kernel_launch(void* const* d_in, const int* in_sizes, int n_in,
                              void* d_out, int out_size)
{
    (void)in_sizes; (void)n_in; (void)out_size;
    const float* x      = (const float*)d_in[0];
    const float* qkv_w  = (const float*)d_in[1];
    const float* qkv_b  = (const float*)d_in[2];
    const float* proj_w = (const float*)d_in[3];
    const float* proj_b = (const float*)d_in[4];
    float* out = (float*)d_out;

    static int attr_done = 0;
    if (!attr_done) {
        cudaFuncSetAttribute(qkv_mma,  cudaFuncAttributeMaxDynamicSharedMemorySize, GEMM_SMEM_BYTES);
        cudaFuncSetAttribute(proj_mma, cudaFuncAttributeMaxDynamicSharedMemorySize, GEMM_SMEM_BYTES);
        attr_done = 1;
    }

    cvt_weights<<<768, 256>>>(qkv_w, proj_w);
    qkv_mma<<<4096, 128, GEMM_SMEM_BYTES>>>(x, qkv_b);
    attn_mma<<<dim3(1024, 4, 8), 128>>>();
    proj_mma<<<4096, 128, GEMM_SMEM_BYTES>>>(proj_b, out);
}